// round 9
// baseline (speedup 1.0000x reference)
#include <cuda_runtime.h>
#include <cuda_fp16.h>
#include <cstdint>
#include <cstddef>

#define N_NODES 50000
#define N_EDGES 500000
#define H 128
#define H3 384
#define SCAN_B 256
#define N_SBLK ((N_NODES + SCAN_B - 1) / SCAN_B)   // 196

// ---------------- scratch (static device allocations, allowed) --------------
__device__ __half2 g_sexp16[(size_t)N_NODES * H3 / 2];  // 38.4 MB (L2-resident)
__device__ __half2 g_v16  [(size_t)N_NODES * H3 / 2];   // 38.4 MB (L2-resident)
// g_state layout: [0, N)        = per-dst degree counts
//                 [N, 2N)       = bucket fill cursors
//                 [2N, 2N+SBLK) = decoupled-lookback scan states
__device__ int    g_state[2 * N_NODES + N_SBLK];
__device__ int    g_start[N_NODES + 1];
__device__ int    g_bsrc [N_EDGES];
__device__ float4 g_bdat [N_EDGES];                      // {d, dir0, dir1, dir2}

// ---------------------------------------------------------------------------
// tf32 helpers (mma.sync m16n8k8, fp32 accumulate)
// ---------------------------------------------------------------------------
__device__ __forceinline__ uint32_t f2tf(float f) {
    uint32_t u;
    asm("cvt.rna.tf32.f32 %0, %1;" : "=r"(u) : "f"(f));
    return u;
}

__device__ __forceinline__ void mma_tf32(float c[4],
                                         uint32_t a0, uint32_t a1,
                                         uint32_t a2, uint32_t a3,
                                         uint32_t b0, uint32_t b1) {
    asm volatile(
        "mma.sync.aligned.m16n8k8.row.col.f32.tf32.tf32.f32 "
        "{%0,%1,%2,%3}, {%4,%5,%6,%7}, {%8,%9}, {%0,%1,%2,%3};"
        : "+f"(c[0]), "+f"(c[1]), "+f"(c[2]), "+f"(c[3])
        : "r"(a0), "r"(a1), "r"(a2), "r"(a3), "r"(b0), "r"(b1));
}

// ---------------------------------------------------------------------------
// Kernel 1: s_exp = tanh(s @ W1 + b1) @ W2 + b2   -> fp16 g_sexp16  [N, 384]
// ---------------------------------------------------------------------------
#define BM 128
#define STR 132
#define SMEM_EMBED_BYTES (2 * 128 * STR * 4)

__device__ __forceinline__ void compute_mma(float acc[4][4][4],
                                            const uint32_t* __restrict__ sA,
                                            const uint32_t* __restrict__ sW,
                                            int wm, int wn, int gid, int tig) {
#pragma unroll
    for (int k = 0; k < 128; k += 8) {
        uint32_t a[4][4];
#pragma unroll
        for (int mt = 0; mt < 4; mt++) {
            int r = wm * 64 + mt * 16 + gid;
            a[mt][0] = sA[r * STR + k + tig];
            a[mt][1] = sA[(r + 8) * STR + k + tig];
            a[mt][2] = sA[r * STR + k + tig + 4];
            a[mt][3] = sA[(r + 8) * STR + k + tig + 4];
        }
#pragma unroll
        for (int nt = 0; nt < 4; nt++) {
            int ncol = wn * 32 + nt * 8 + gid;
            uint32_t b0 = sW[(k + tig) * STR + ncol];
            uint32_t b1 = sW[(k + tig + 4) * STR + ncol];
#pragma unroll
            for (int mt = 0; mt < 4; mt++)
                mma_tf32(acc[mt][nt], a[mt][0], a[mt][1], a[mt][2], a[mt][3],
                         b0, b1);
        }
    }
}

__global__ __launch_bounds__(256) void embed_kernel(
    const float* __restrict__ s,
    const float* __restrict__ W1, const float* __restrict__ b1,
    const float* __restrict__ W2, const float* __restrict__ b2)
{
    extern __shared__ uint32_t smem_u[];
    uint32_t* sS = smem_u;
    uint32_t* sW = smem_u + 128 * STR;

    const int t    = threadIdx.x;
    const int r0   = blockIdx.x * BM;
    const int wid  = t >> 5, lane = t & 31;
    const int wm   = wid & 1, wn = wid >> 1;
    const int gid  = lane >> 2, tig = lane & 3;

#pragma unroll
    for (int i = 0; i < 16; i++) {
        int idx4 = t + i * 256;
        int row  = idx4 >> 5;
        int c4   = (idx4 & 31) * 4;
        float4 val = make_float4(0.f, 0.f, 0.f, 0.f);
        if (r0 + row < N_NODES)
            val = *(const float4*)(s + (size_t)(r0 + row) * H + c4);
        uint32_t* p = sS + row * STR + c4;
        p[0] = f2tf(val.x); p[1] = f2tf(val.y);
        p[2] = f2tf(val.z); p[3] = f2tf(val.w);
    }
#pragma unroll
    for (int i = 0; i < 16; i++) {
        int idx4 = t + i * 256;
        int row  = idx4 >> 5;
        int c4   = (idx4 & 31) * 4;
        float4 val = *(const float4*)(W1 + (size_t)row * H + c4);
        uint32_t* p = sW + row * STR + c4;
        p[0] = f2tf(val.x); p[1] = f2tf(val.y);
        p[2] = f2tf(val.z); p[3] = f2tf(val.w);
    }
    __syncthreads();

    float acc[4][4][4];
#pragma unroll
    for (int mt = 0; mt < 4; mt++)
#pragma unroll
        for (int nt = 0; nt < 4; nt++)
#pragma unroll
            for (int i = 0; i < 4; i++) acc[mt][nt][i] = 0.f;

    compute_mma(acc, sS, sW, wm, wn, gid, tig);
    __syncthreads();

#pragma unroll
    for (int mt = 0; mt < 4; mt++) {
        int row = wm * 64 + mt * 16 + gid;
#pragma unroll
        for (int nt = 0; nt < 4; nt++) {
            int col = wn * 32 + nt * 8 + tig * 2;
            float ba = __ldg(b1 + col), bb = __ldg(b1 + col + 1);
            sS[row * STR + col]           = f2tf(tanhf(acc[mt][nt][0] + ba));
            sS[row * STR + col + 1]       = f2tf(tanhf(acc[mt][nt][1] + bb));
            sS[(row + 8) * STR + col]     = f2tf(tanhf(acc[mt][nt][2] + ba));
            sS[(row + 8) * STR + col + 1] = f2tf(tanhf(acc[mt][nt][3] + bb));
        }
    }

    for (int chunk = 0; chunk < 3; chunk++) {
        __syncthreads();
#pragma unroll
        for (int i = 0; i < 16; i++) {
            int idx4 = t + i * 256;
            int row  = idx4 >> 5;
            int c4   = (idx4 & 31) * 4;
            float4 val = *(const float4*)(W2 + (size_t)row * H3
                                          + chunk * 128 + c4);
            uint32_t* p = sW + row * STR + c4;
            p[0] = f2tf(val.x); p[1] = f2tf(val.y);
            p[2] = f2tf(val.z); p[3] = f2tf(val.w);
        }
        __syncthreads();

        float acc2[4][4][4];
#pragma unroll
        for (int mt = 0; mt < 4; mt++)
#pragma unroll
            for (int nt = 0; nt < 4; nt++)
#pragma unroll
                for (int i = 0; i < 4; i++) acc2[mt][nt][i] = 0.f;

        compute_mma(acc2, sS, sW, wm, wn, gid, tig);

#pragma unroll
        for (int mt = 0; mt < 4; mt++) {
            int rl = wm * 64 + mt * 16 + gid;
#pragma unroll
            for (int nt = 0; nt < 4; nt++) {
                int col = chunk * 128 + wn * 32 + nt * 8 + tig * 2;
                float ba = __ldg(b2 + col), bb = __ldg(b2 + col + 1);
                int row = r0 + rl;
                if (row < N_NODES)
                    g_sexp16[(size_t)row * (H3 / 2) + (col >> 1)] =
                        __floats2half2_rn(acc2[mt][nt][0] + ba,
                                          acc2[mt][nt][1] + bb);
                if (row + 8 < N_NODES)
                    g_sexp16[(size_t)(row + 8) * (H3 / 2) + (col >> 1)] =
                        __floats2half2_rn(acc2[mt][nt][2] + ba,
                                          acc2[mt][nt][3] + bb);
            }
        }
    }
}

// ---------------------------------------------------------------------------
// v -> fp16 conversion (streaming read) fused with dst histogram
// ---------------------------------------------------------------------------
__global__ __launch_bounds__(256) void vconv_hist_kernel(
    const float* __restrict__ v, const int* __restrict__ ei)
{
    size_t i = (size_t)blockIdx.x * 256 + threadIdx.x;
    const size_t n2 = (size_t)N_NODES * H3 / 2;
    if (i < n2) {
        float2 f = __ldcs((const float2*)v + i);
        g_v16[i] = __floats2half2_rn(f.x, f.y);
    }
    if (i < N_EDGES)
        atomicAdd(&g_state[__ldg(ei + N_EDGES + (int)i)], 1);
}

// ---------------------------------------------------------------------------
// Single-kernel exclusive scan (decoupled lookback), 196 blocks x 256.
// Produces g_start[0..N_NODES].
// ---------------------------------------------------------------------------
__global__ __launch_bounds__(SCAN_B) void scan_lb_kernel() {
    __shared__ int tmp[SCAN_B];
    __shared__ int s_prefix;
    const int b = blockIdx.x;
    const int t = threadIdx.x;
    const int idx = b * SCAN_B + t;
    int* states = g_state + 2 * N_NODES;

    int v = (idx < N_NODES) ? g_state[idx] : 0;
    tmp[t] = v;
    __syncthreads();
#pragma unroll
    for (int off = 1; off < SCAN_B; off <<= 1) {
        int u = (t >= off) ? tmp[t - off] : 0;
        __syncthreads();
        tmp[t] += u;
        __syncthreads();
    }
    const int incl = tmp[t];
    const int total = tmp[SCAN_B - 1];

    if (t == 0) {
        if (b == 0) {
            __threadfence();
            atomicExch(&states[0], (total << 2) | 2);   // PREFIX
            s_prefix = 0;
        } else {
            __threadfence();
            atomicExch(&states[b], (total << 2) | 1);   // AGGREGATE
            int run = 0;
            int i = b - 1;
            while (true) {
                int st;
                do { st = atomicAdd(&states[i], 0); } while ((st & 3) == 0);
                run += (st >> 2);
                if ((st & 3) == 2) break;
                --i;
            }
            s_prefix = run;
            __threadfence();
            atomicExch(&states[b], ((run + total) << 2) | 2);
        }
    }
    __syncthreads();

    if (idx < N_NODES) g_start[idx] = s_prefix + incl - v;   // exclusive
    if (idx == 0)      g_start[N_NODES] = N_EDGES;
}

// ---------------------------------------------------------------------------
// Bucket fill (payload materialized, grouped by dst)
// ---------------------------------------------------------------------------
__global__ __launch_bounds__(256) void fill_kernel(
    const int* __restrict__ ei,
    const float* __restrict__ dij,
    const float* __restrict__ dir)
{
    int e = blockIdx.x * 256 + threadIdx.x;
    if (e >= N_EDGES) return;
    int dst = __ldg(ei + N_EDGES + e);
    int pos = g_start[dst] + atomicAdd(&g_state[N_NODES + dst], 1);
    g_bsrc[pos] = __ldg(ei + e);
    g_bdat[pos] = make_float4(__ldcs(dij + e), __ldcs(dir + 3 * e),
                              __ldcs(dir + 3 * e + 1), __ldcs(dir + 3 * e + 2));
}

// ---------------------------------------------------------------------------
// Kernel 2: gather + finalize. One WARP per node (32 lanes x 4 cols, 8B
// gathers). Streaming accesses use evict-first hints so the fp16 gather
// arrays stay L2-resident.
// ---------------------------------------------------------------------------
__global__ __launch_bounds__(256) void gather_kernel(
    const float* __restrict__ v,
    const float* __restrict__ s,
    const float* __restrict__ Wd,
    const float* __restrict__ bd,
    float* __restrict__ out)
{
    const int t    = threadIdx.x;
    const int node = blockIdx.x * 8 + (t >> 5);
    const int c    = t & 31;

    const int beg = g_start[node];
    const int end = g_start[node + 1];

    const float4 wv = *(const float4*)(Wd + 4 * c);
    const float4 bv = *(const float4*)(bd + 4 * c);
    const float4 ws = *(const float4*)(Wd + 128 + 4 * c);
    const float4 bs = *(const float4*)(bd + 128 + 4 * c);
    const float4 wr = *(const float4*)(Wd + 256 + 4 * c);
    const float4 br = *(const float4*)(bd + 256 + 4 * c);

    float4 accs = make_float4(0.f, 0.f, 0.f, 0.f);
    float4 a0 = accs, a1 = accs, a2 = accs;

    const uint2* sbase   = (const uint2*)g_sexp16;
    const uint2* vbase16 = (const uint2*)g_v16;

#pragma unroll 4
    for (int j = beg; j < end; j++) {
        const int src = __ldcs(g_bsrc + j);
        const float4 ed = __ldcs(g_bdat + j);    // {d, d0, d1, d2}

        const uint2* sx = sbase + (size_t)src * 96;
        const uint2* vx = vbase16 + (size_t)src * 96;
        const uint2 uev = __ldg(sx + c);
        const uint2 ues = __ldg(sx + 32 + c);
        const uint2 uer = __ldg(sx + 64 + c);
        const uint2 uv0 = __ldg(vx + c);
        const uint2 uv1 = __ldg(vx + 32 + c);
        const uint2 uv2 = __ldg(vx + 64 + c);

        const float2 evA = __half22float2(*(const __half2*)&uev.x);
        const float2 evB = __half22float2(*(const __half2*)&uev.y);
        const float2 esA = __half22float2(*(const __half2*)&ues.x);
        const float2 esB = __half22float2(*(const __half2*)&ues.y);
        const float2 erA = __half22float2(*(const __half2*)&uer.x);
        const float2 erB = __half22float2(*(const __half2*)&uer.y);
        const float2 v0A = __half22float2(*(const __half2*)&uv0.x);
        const float2 v0B = __half22float2(*(const __half2*)&uv0.y);
        const float2 v1A = __half22float2(*(const __half2*)&uv1.x);
        const float2 v1B = __half22float2(*(const __half2*)&uv1.y);
        const float2 v2A = __half22float2(*(const __half2*)&uv2.x);
        const float2 v2B = __half22float2(*(const __half2*)&uv2.y);

        const float gv0 = evA.x * fmaf(ed.x, wv.x, bv.x);
        const float gv1 = evA.y * fmaf(ed.x, wv.y, bv.y);
        const float gv2 = evB.x * fmaf(ed.x, wv.z, bv.z);
        const float gv3 = evB.y * fmaf(ed.x, wv.w, bv.w);
        const float gr0 = erA.x * fmaf(ed.x, wr.x, br.x);
        const float gr1 = erA.y * fmaf(ed.x, wr.y, br.y);
        const float gr2 = erB.x * fmaf(ed.x, wr.z, br.z);
        const float gr3 = erB.y * fmaf(ed.x, wr.w, br.w);

        accs.x = fmaf(esA.x, fmaf(ed.x, ws.x, bs.x), accs.x);
        accs.y = fmaf(esA.y, fmaf(ed.x, ws.y, bs.y), accs.y);
        accs.z = fmaf(esB.x, fmaf(ed.x, ws.z, bs.z), accs.z);
        accs.w = fmaf(esB.y, fmaf(ed.x, ws.w, bs.w), accs.w);

        a0.x = fmaf(gr0, ed.y, fmaf(gv0, v0A.x, a0.x));
        a0.y = fmaf(gr1, ed.y, fmaf(gv1, v0A.y, a0.y));
        a0.z = fmaf(gr2, ed.y, fmaf(gv2, v0B.x, a0.z));
        a0.w = fmaf(gr3, ed.y, fmaf(gv3, v0B.y, a0.w));
        a1.x = fmaf(gr0, ed.z, fmaf(gv0, v1A.x, a1.x));
        a1.y = fmaf(gr1, ed.z, fmaf(gv1, v1A.y, a1.y));
        a1.z = fmaf(gr2, ed.z, fmaf(gv2, v1B.x, a1.z));
        a1.w = fmaf(gr3, ed.z, fmaf(gv3, v1B.y, a1.w));
        a2.x = fmaf(gr0, ed.w, fmaf(gv0, v2A.x, a2.x));
        a2.y = fmaf(gr1, ed.w, fmaf(gv1, v2A.y, a2.y));
        a2.z = fmaf(gr2, ed.w, fmaf(gv2, v2B.x, a2.z));
        a2.w = fmaf(gr3, ed.w, fmaf(gv3, v2B.y, a2.w));
    }

    const float inv = 1.0f / fmaxf((float)(end - beg), 1.0f);

    const size_t vb = (size_t)node * H3;
    float4 x, o;
    x = __ldcs((const float4*)(v + vb + 4 * c));
    o = make_float4(fmaf(a0.x, inv, x.x), fmaf(a0.y, inv, x.y),
                    fmaf(a0.z, inv, x.z), fmaf(a0.w, inv, x.w));
    __stcs((float4*)(out + vb + 4 * c), o);
    x = __ldcs((const float4*)(v + vb + 128 + 4 * c));
    o = make_float4(fmaf(a1.x, inv, x.x), fmaf(a1.y, inv, x.y),
                    fmaf(a1.z, inv, x.z), fmaf(a1.w, inv, x.w));
    __stcs((float4*)(out + vb + 128 + 4 * c), o);
    x = __ldcs((const float4*)(v + vb + 256 + 4 * c));
    o = make_float4(fmaf(a2.x, inv, x.x), fmaf(a2.y, inv, x.y),
                    fmaf(a2.z, inv, x.z), fmaf(a2.w, inv, x.w));
    __stcs((float4*)(out + vb + 256 + 4 * c), o);

    x = __ldcs((const float4*)(s + (size_t)node * H + 4 * c));
    o = make_float4(fmaf(accs.x, inv, x.x), fmaf(accs.y, inv, x.y),
                    fmaf(accs.z, inv, x.z), fmaf(accs.w, inv, x.w));
    __stcs((float4*)(out + (size_t)N_NODES * H3 + (size_t)node * H + 4 * c), o);
}

// ---------------------------------------------------------------------------
extern "C" void kernel_launch(void* const* d_in, const int* in_sizes, int n_in,
                              void* d_out, int out_size) {
    const float* v   = (const float*)d_in[0];
    const float* s   = (const float*)d_in[1];
    const int*   ei  = (const int*)  d_in[2];
    const float* dij = (const float*)d_in[3];
    const float* dir = (const float*)d_in[4];
    const float* W1  = (const float*)d_in[5];
    const float* b1  = (const float*)d_in[6];
    const float* W2  = (const float*)d_in[7];
    const float* b2  = (const float*)d_in[8];
    const float* Wd  = (const float*)d_in[9];
    const float* bd  = (const float*)d_in[10];
    float* out = (float*)d_out;

    cudaFuncSetAttribute(embed_kernel,
                         cudaFuncAttributeMaxDynamicSharedMemorySize,
                         SMEM_EMBED_BYTES);

    void* pstate;
    cudaGetSymbolAddress(&pstate, g_state);
    cudaMemsetAsync(pstate, 0, sizeof(int) * (2 * N_NODES + N_SBLK), 0);

    const size_t n2 = (size_t)N_NODES * H3 / 2;   // 4.8M
    embed_kernel<<<(N_NODES + BM - 1) / BM, 256, SMEM_EMBED_BYTES>>>(
        s, W1, b1, W2, b2);
    vconv_hist_kernel<<<(int)((n2 + 255) / 256), 256>>>(v, ei);
    scan_lb_kernel<<<N_SBLK, SCAN_B>>>();
    fill_kernel<<<(N_EDGES + 255) / 256, 256>>>(ei, dij, dir);
    gather_kernel<<<(N_NODES + 7) / 8, 256>>>(v, s, Wd, bd, out);
}

// round 11
// speedup vs baseline: 1.0573x; 1.0573x over previous
#include <cuda_runtime.h>
#include <cuda_fp16.h>
#include <cstdint>
#include <cstddef>

#define N_NODES 50000
#define N_EDGES 500000
#define H 128
#define H3 384
#define SCAN_B 256
#define N_SBLK ((N_NODES + SCAN_B - 1) / SCAN_B)   // 196

// ---------------- scratch (static device allocations, allowed) --------------
__device__ __half2 g_sexp16[(size_t)N_NODES * H3 / 2];  // 38.4 MB
__device__ __half2 g_v16  [(size_t)N_NODES * H3 / 2];   // 38.4 MB
__device__ int    g_count[N_NODES];
__device__ int    g_fill [N_NODES];
__device__ int    g_start[N_NODES + 1];
__device__ int    g_bsum [N_SBLK];
__device__ int    g_boff [N_SBLK];
__device__ int    g_bsrc [N_EDGES];                      // src per bucket slot
__device__ float4 g_bdat [N_EDGES];                      // {d, dir0, dir1, dir2}

// ---------------------------------------------------------------------------
// tf32 helpers (mma.sync m16n8k8, fp32 accumulate)
// ---------------------------------------------------------------------------
__device__ __forceinline__ uint32_t f2tf(float f) {
    uint32_t u;
    asm("cvt.rna.tf32.f32 %0, %1;" : "=r"(u) : "f"(f));
    return u;
}

__device__ __forceinline__ void mma_tf32(float c[4],
                                         uint32_t a0, uint32_t a1,
                                         uint32_t a2, uint32_t a3,
                                         uint32_t b0, uint32_t b1) {
    asm volatile(
        "mma.sync.aligned.m16n8k8.row.col.f32.tf32.tf32.f32 "
        "{%0,%1,%2,%3}, {%4,%5,%6,%7}, {%8,%9}, {%0,%1,%2,%3};"
        : "+f"(c[0]), "+f"(c[1]), "+f"(c[2]), "+f"(c[3])
        : "r"(a0), "r"(a1), "r"(a2), "r"(a3), "r"(b0), "r"(b1));
}

// evict_last access policy (created once per thread)
__device__ __forceinline__ uint64_t mk_policy_el() {
    uint64_t pol;
    asm("createpolicy.fractional.L2::evict_last.b64 %0, 1.0;" : "=l"(pol));
    return pol;
}

// gather load with L2 evict_last cache hint
__device__ __forceinline__ __half2 ldg_el(const __half2* p, uint64_t pol) {
    uint32_t u;
    asm volatile("ld.global.nc.L2::cache_hint.b32 %0, [%1], %2;"
                 : "=r"(u) : "l"(p), "l"(pol));
    return *reinterpret_cast<__half2*>(&u);
}

// ---------------------------------------------------------------------------
// Kernel 1: s_exp = tanh(s @ W1 + b1) @ W2 + b2   -> fp16 g_sexp16  [N, 384]
// Block: 128 rows, 256 threads (8 warps). Warp: 64x32 via 4x4 m16n8k8 tiles.
// ---------------------------------------------------------------------------
#define BM 128
#define STR 132
#define SMEM_EMBED_BYTES (2 * 128 * STR * 4)

__device__ __forceinline__ void compute_mma(float acc[4][4][4],
                                            const uint32_t* __restrict__ sA,
                                            const uint32_t* __restrict__ sW,
                                            int wm, int wn, int gid, int tig) {
#pragma unroll
    for (int k = 0; k < 128; k += 8) {
        uint32_t a[4][4];
#pragma unroll
        for (int mt = 0; mt < 4; mt++) {
            int r = wm * 64 + mt * 16 + gid;
            a[mt][0] = sA[r * STR + k + tig];
            a[mt][1] = sA[(r + 8) * STR + k + tig];
            a[mt][2] = sA[r * STR + k + tig + 4];
            a[mt][3] = sA[(r + 8) * STR + k + tig + 4];
        }
#pragma unroll
        for (int nt = 0; nt < 4; nt++) {
            int ncol = wn * 32 + nt * 8 + gid;
            uint32_t b0 = sW[(k + tig) * STR + ncol];
            uint32_t b1 = sW[(k + tig + 4) * STR + ncol];
#pragma unroll
            for (int mt = 0; mt < 4; mt++)
                mma_tf32(acc[mt][nt], a[mt][0], a[mt][1], a[mt][2], a[mt][3],
                         b0, b1);
        }
    }
}

__global__ __launch_bounds__(256) void embed_kernel(
    const float* __restrict__ s,
    const float* __restrict__ W1, const float* __restrict__ b1,
    const float* __restrict__ W2, const float* __restrict__ b2)
{
    extern __shared__ uint32_t smem_u[];
    uint32_t* sS = smem_u;               // 128 x STR (tf32)
    uint32_t* sW = smem_u + 128 * STR;   // 128 x STR (tf32)

    const int t    = threadIdx.x;
    const int r0   = blockIdx.x * BM;
    const int wid  = t >> 5, lane = t & 31;
    const int wm   = wid & 1, wn = wid >> 1;
    const int gid  = lane >> 2, tig = lane & 3;

#pragma unroll
    for (int i = 0; i < 16; i++) {
        int idx4 = t + i * 256;
        int row  = idx4 >> 5;
        int c4   = (idx4 & 31) * 4;
        float4 val = make_float4(0.f, 0.f, 0.f, 0.f);
        if (r0 + row < N_NODES)
            val = *(const float4*)(s + (size_t)(r0 + row) * H + c4);
        uint32_t* p = sS + row * STR + c4;
        p[0] = f2tf(val.x); p[1] = f2tf(val.y);
        p[2] = f2tf(val.z); p[3] = f2tf(val.w);
    }
#pragma unroll
    for (int i = 0; i < 16; i++) {
        int idx4 = t + i * 256;
        int row  = idx4 >> 5;
        int c4   = (idx4 & 31) * 4;
        float4 val = *(const float4*)(W1 + (size_t)row * H + c4);
        uint32_t* p = sW + row * STR + c4;
        p[0] = f2tf(val.x); p[1] = f2tf(val.y);
        p[2] = f2tf(val.z); p[3] = f2tf(val.w);
    }
    __syncthreads();

    float acc[4][4][4];
#pragma unroll
    for (int mt = 0; mt < 4; mt++)
#pragma unroll
        for (int nt = 0; nt < 4; nt++)
#pragma unroll
            for (int i = 0; i < 4; i++) acc[mt][nt][i] = 0.f;

    compute_mma(acc, sS, sW, wm, wn, gid, tig);
    __syncthreads();

#pragma unroll
    for (int mt = 0; mt < 4; mt++) {
        int row = wm * 64 + mt * 16 + gid;
#pragma unroll
        for (int nt = 0; nt < 4; nt++) {
            int col = wn * 32 + nt * 8 + tig * 2;
            float ba = __ldg(b1 + col), bb = __ldg(b1 + col + 1);
            sS[row * STR + col]           = f2tf(tanhf(acc[mt][nt][0] + ba));
            sS[row * STR + col + 1]       = f2tf(tanhf(acc[mt][nt][1] + bb));
            sS[(row + 8) * STR + col]     = f2tf(tanhf(acc[mt][nt][2] + ba));
            sS[(row + 8) * STR + col + 1] = f2tf(tanhf(acc[mt][nt][3] + bb));
        }
    }

    for (int chunk = 0; chunk < 3; chunk++) {
        __syncthreads();
#pragma unroll
        for (int i = 0; i < 16; i++) {
            int idx4 = t + i * 256;
            int row  = idx4 >> 5;
            int c4   = (idx4 & 31) * 4;
            float4 val = *(const float4*)(W2 + (size_t)row * H3
                                          + chunk * 128 + c4);
            uint32_t* p = sW + row * STR + c4;
            p[0] = f2tf(val.x); p[1] = f2tf(val.y);
            p[2] = f2tf(val.z); p[3] = f2tf(val.w);
        }
        __syncthreads();

        float acc2[4][4][4];
#pragma unroll
        for (int mt = 0; mt < 4; mt++)
#pragma unroll
            for (int nt = 0; nt < 4; nt++)
#pragma unroll
                for (int i = 0; i < 4; i++) acc2[mt][nt][i] = 0.f;

        compute_mma(acc2, sS, sW, wm, wn, gid, tig);

#pragma unroll
        for (int mt = 0; mt < 4; mt++) {
            int rl = wm * 64 + mt * 16 + gid;
#pragma unroll
            for (int nt = 0; nt < 4; nt++) {
                int col = chunk * 128 + wn * 32 + nt * 8 + tig * 2;
                float ba = __ldg(b2 + col), bb = __ldg(b2 + col + 1);
                int row = r0 + rl;
                if (row < N_NODES)
                    g_sexp16[(size_t)row * (H3 / 2) + (col >> 1)] =
                        __floats2half2_rn(acc2[mt][nt][0] + ba,
                                          acc2[mt][nt][1] + bb);
                if (row + 8 < N_NODES)
                    g_sexp16[(size_t)(row + 8) * (H3 / 2) + (col >> 1)] =
                        __floats2half2_rn(acc2[mt][nt][2] + ba,
                                          acc2[mt][nt][3] + bb);
            }
        }
    }
}

// ---------------------------------------------------------------------------
// v -> fp16 streaming conversion
// ---------------------------------------------------------------------------
__global__ __launch_bounds__(256) void vconv_kernel(const float* __restrict__ v) {
    size_t i = (size_t)blockIdx.x * 256 + threadIdx.x;
    const size_t n2 = (size_t)N_NODES * H3 / 2;
    if (i < n2) {
        float2 f = ((const float2*)v)[i];
        g_v16[i] = __floats2half2_rn(f.x, f.y);
    }
}

// ---------------------------------------------------------------------------
// CSR build: histogram -> two-level scan -> bucket fill (with payload)
// ---------------------------------------------------------------------------
__global__ __launch_bounds__(256) void hist_kernel(const int* __restrict__ ei) {
    int i = blockIdx.x * 256 + threadIdx.x;
    if (i < N_EDGES) atomicAdd(&g_count[__ldg(ei + N_EDGES + i)], 1);
}

__global__ __launch_bounds__(SCAN_B) void scan1_kernel() {
    __shared__ int red[SCAN_B / 32];
    const int idx = blockIdx.x * SCAN_B + threadIdx.x;
    int val = (idx < N_NODES) ? g_count[idx] : 0;
#pragma unroll
    for (int o = 16; o > 0; o >>= 1)
        val += __shfl_down_sync(0xffffffffu, val, o);
    if ((threadIdx.x & 31) == 0) red[threadIdx.x >> 5] = val;
    __syncthreads();
    if (threadIdx.x < SCAN_B / 32) {
        int v = red[threadIdx.x];
#pragma unroll
        for (int o = SCAN_B / 64; o > 0; o >>= 1)
            v += __shfl_down_sync(0xffu, v, o);
        if (threadIdx.x == 0) g_bsum[blockIdx.x] = v;
    }
}

__global__ __launch_bounds__(256) void scan2_kernel() {
    __shared__ int tmp[256];
    const int t = threadIdx.x;
    int v = (t < N_SBLK) ? g_bsum[t] : 0;
    tmp[t] = v;
    __syncthreads();
#pragma unroll
    for (int off = 1; off < 256; off <<= 1) {
        int u = (t >= off) ? tmp[t - off] : 0;
        __syncthreads();
        tmp[t] += u;
        __syncthreads();
    }
    if (t < N_SBLK) g_boff[t] = tmp[t] - v;   // exclusive
    if (t == 0) g_start[N_NODES] = N_EDGES;
}

__global__ __launch_bounds__(SCAN_B) void scan3_kernel() {
    __shared__ int tmp[SCAN_B];
    const int t = threadIdx.x;
    const int idx = blockIdx.x * SCAN_B + t;
    int v = (idx < N_NODES) ? g_count[idx] : 0;
    tmp[t] = v;
    __syncthreads();
#pragma unroll
    for (int off = 1; off < SCAN_B; off <<= 1) {
        int u = (t >= off) ? tmp[t - off] : 0;
        __syncthreads();
        tmp[t] += u;
        __syncthreads();
    }
    if (idx < N_NODES)
        g_start[idx] = g_boff[blockIdx.x] + tmp[t] - v;
}

__global__ __launch_bounds__(256) void fill_kernel(
    const int* __restrict__ ei,
    const float* __restrict__ dij,
    const float* __restrict__ dir)
{
    int e = blockIdx.x * 256 + threadIdx.x;
    if (e >= N_EDGES) return;
    int dst = __ldg(ei + N_EDGES + e);
    int pos = g_start[dst] + atomicAdd(&g_fill[dst], 1);
    g_bsrc[pos] = __ldg(ei + e);
    g_bdat[pos] = make_float4(__ldg(dij + e), __ldg(dir + 3 * e),
                              __ldg(dir + 3 * e + 1), __ldg(dir + 3 * e + 2));
}

// ---------------------------------------------------------------------------
// Kernel 2: gather + finalize. 128-thread block = 2 nodes x 64 threads.
// Thread owns half2 column pair c. Gather loads use evict_last cache policy.
// ---------------------------------------------------------------------------
__global__ __launch_bounds__(128) void gather_kernel(
    const float* __restrict__ v,
    const float* __restrict__ s,
    const float* __restrict__ Wd,
    const float* __restrict__ bd,
    float* __restrict__ out)
{
    const int t    = threadIdx.x;
    const int node = blockIdx.x * 2 + (t >> 6);
    const int c    = t & 63;                 // half2 column index, 0..63

    const int beg = g_start[node];
    const int end = g_start[node + 1];

    const uint64_t pol = mk_policy_el();

    const float2 wv = *(const float2*)(Wd + 2 * c);
    const float2 bv = *(const float2*)(bd + 2 * c);
    const float2 ws = *(const float2*)(Wd + 128 + 2 * c);
    const float2 bs = *(const float2*)(bd + 128 + 2 * c);
    const float2 wr = *(const float2*)(Wd + 256 + 2 * c);
    const float2 br = *(const float2*)(bd + 256 + 2 * c);

    float2 accs = make_float2(0.f, 0.f);
    float2 a0 = accs, a1 = accs, a2 = accs;

#pragma unroll 4
    for (int j = beg; j < end; j++) {
        const int src = __ldg(g_bsrc + j);
        const float4 ed = __ldg(g_bdat + j);    // {d, d0, d1, d2}

        const __half2* sx = g_sexp16 + (size_t)src * 192;
        const float2 ev = __half22float2(ldg_el(sx + c, pol));
        const float2 es = __half22float2(ldg_el(sx + 64 + c, pol));
        const float2 er = __half22float2(ldg_el(sx + 128 + c, pol));

        const float gvx = ev.x * fmaf(ed.x, wv.x, bv.x);
        const float gvy = ev.y * fmaf(ed.x, wv.y, bv.y);
        const float grx = er.x * fmaf(ed.x, wr.x, br.x);
        const float gry = er.y * fmaf(ed.x, wr.y, br.y);

        accs.x = fmaf(es.x, fmaf(ed.x, ws.x, bs.x), accs.x);
        accs.y = fmaf(es.y, fmaf(ed.x, ws.y, bs.y), accs.y);

        const __half2* vb = g_v16 + (size_t)src * 192;
        const float2 v0 = __half22float2(ldg_el(vb + c, pol));
        const float2 v1 = __half22float2(ldg_el(vb + 64 + c, pol));
        const float2 v2 = __half22float2(ldg_el(vb + 128 + c, pol));

        a0.x = fmaf(grx, ed.y, fmaf(gvx, v0.x, a0.x));
        a0.y = fmaf(gry, ed.y, fmaf(gvy, v0.y, a0.y));
        a1.x = fmaf(grx, ed.z, fmaf(gvx, v1.x, a1.x));
        a1.y = fmaf(gry, ed.z, fmaf(gvy, v1.y, a1.y));
        a2.x = fmaf(grx, ed.w, fmaf(gvx, v2.x, a2.x));
        a2.y = fmaf(gry, ed.w, fmaf(gvy, v2.y, a2.y));
    }

    const float inv = 1.0f / fmaxf((float)(end - beg), 1.0f);

    const size_t vb = (size_t)node * H3;
    float2 o;
    float2 x0 = *(const float2*)(v + vb + 2 * c);
    o = make_float2(fmaf(a0.x, inv, x0.x), fmaf(a0.y, inv, x0.y));
    *(float2*)(out + vb + 2 * c) = o;
    float2 x1 = *(const float2*)(v + vb + 128 + 2 * c);
    o = make_float2(fmaf(a1.x, inv, x1.x), fmaf(a1.y, inv, x1.y));
    *(float2*)(out + vb + 128 + 2 * c) = o;
    float2 x2 = *(const float2*)(v + vb + 256 + 2 * c);
    o = make_float2(fmaf(a2.x, inv, x2.x), fmaf(a2.y, inv, x2.y));
    *(float2*)(out + vb + 256 + 2 * c) = o;

    float2 xs = *(const float2*)(s + (size_t)node * H + 2 * c);
    o = make_float2(fmaf(accs.x, inv, xs.x), fmaf(accs.y, inv, xs.y));
    *(float2*)(out + (size_t)N_NODES * H3 + (size_t)node * H + 2 * c) = o;
}

// ---------------------------------------------------------------------------
extern "C" void kernel_launch(void* const* d_in, const int* in_sizes, int n_in,
                              void* d_out, int out_size) {
    const float* v   = (const float*)d_in[0];
    const float* s   = (const float*)d_in[1];
    const int*   ei  = (const int*)  d_in[2];
    const float* dij = (const float*)d_in[3];
    const float* dir = (const float*)d_in[4];
    const float* W1  = (const float*)d_in[5];
    const float* b1  = (const float*)d_in[6];
    const float* W2  = (const float*)d_in[7];
    const float* b2  = (const float*)d_in[8];
    const float* Wd  = (const float*)d_in[9];
    const float* bd  = (const float*)d_in[10];
    float* out = (float*)d_out;

    cudaFuncSetAttribute(embed_kernel,
                         cudaFuncAttributeMaxDynamicSharedMemorySize,
                         SMEM_EMBED_BYTES);

    void *pcnt, *pfill;
    cudaGetSymbolAddress(&pcnt,  g_count);
    cudaGetSymbolAddress(&pfill, g_fill);
    cudaMemsetAsync(pcnt,  0, sizeof(int) * N_NODES, 0);
    cudaMemsetAsync(pfill, 0, sizeof(int) * N_NODES, 0);

    embed_kernel<<<(N_NODES + BM - 1) / BM, 256, SMEM_EMBED_BYTES>>>(
        s, W1, b1, W2, b2);
    vconv_kernel<<<(int)(((size_t)N_NODES * H3 / 2 + 255) / 256), 256>>>(v);
    hist_kernel<<<(N_EDGES + 255) / 256, 256>>>(ei);
    scan1_kernel<<<N_SBLK, SCAN_B>>>();
    scan2_kernel<<<1, 256>>>();
    scan3_kernel<<<N_SBLK, SCAN_B>>>();
    fill_kernel<<<(N_EDGES + 255) / 256, 256>>>(ei, dij, dir);
    gather_kernel<<<(N_NODES + 1) / 2, 128>>>(v, s, Wd, bd, out);
}

// round 12
// speedup vs baseline: 1.1647x; 1.1016x over previous
#include <cuda_runtime.h>
#include <cuda_fp16.h>
#include <cstdint>
#include <cstddef>

#define N_NODES 50000
#define N_EDGES 500000
#define H 128
#define H3 384
#define SCAN_B 256
#define N_SBLK ((N_NODES + SCAN_B - 1) / SCAN_B)   // 196

// ---------------- scratch (static device allocations, allowed) --------------
__device__ __half2 g_sexp16[(size_t)N_NODES * H3 / 2];  // 38.4 MB
__device__ __half2 g_v16  [(size_t)N_NODES * H3 / 2];   // 38.4 MB
__device__ int    g_count[N_NODES];
__device__ int    g_fill [N_NODES];
__device__ int    g_start[N_NODES + 1];
__device__ int    g_bsum [N_SBLK];
__device__ int    g_boff [N_SBLK];
__device__ int    g_bsrc [N_EDGES];                      // src per bucket slot
__device__ float4 g_bdat [N_EDGES];                      // {d, dir0, dir1, dir2}

// ---------------------------------------------------------------------------
// fp16 mma helpers (m16n8k16, fp32 accumulate) + ldmatrix
// ---------------------------------------------------------------------------
__device__ __forceinline__ void mma_f16(float c[4],
                                        uint32_t a0, uint32_t a1,
                                        uint32_t a2, uint32_t a3,
                                        uint32_t b0, uint32_t b1) {
    asm volatile(
        "mma.sync.aligned.m16n8k16.row.col.f32.f16.f16.f32 "
        "{%0,%1,%2,%3}, {%4,%5,%6,%7}, {%8,%9}, {%0,%1,%2,%3};"
        : "+f"(c[0]), "+f"(c[1]), "+f"(c[2]), "+f"(c[3])
        : "r"(a0), "r"(a1), "r"(a2), "r"(a3), "r"(b0), "r"(b1));
}

__device__ __forceinline__ void ldsm_x4(uint32_t r[4], uint32_t addr) {
    asm volatile("ldmatrix.sync.aligned.m8n8.x4.shared.b16 {%0,%1,%2,%3}, [%4];"
                 : "=r"(r[0]), "=r"(r[1]), "=r"(r[2]), "=r"(r[3]) : "r"(addr));
}

__device__ __forceinline__ void ldsm_x2t(uint32_t& b0, uint32_t& b1,
                                         uint32_t addr) {
    asm volatile("ldmatrix.sync.aligned.m8n8.x2.trans.shared.b16 {%0,%1}, [%2];"
                 : "=r"(b0), "=r"(b1) : "r"(addr));
}

// ---------------------------------------------------------------------------
// Kernel 1: s_exp = tanh(s @ W1 + b1) @ W2 + b2  -> fp16 g_sexp16  [N, 384]
// Block: 128 rows, 256 threads (8 warps: wm 0..1 x wn 0..3).
// Warp: 64 rows x 32 cols via 4x4 m16n8k16 fp16 mma tiles. A and W tiles in
// fp16 smem (stride 136 halves, conflict-free ldmatrix). 69.6 KB -> 2 blk/SM.
// ---------------------------------------------------------------------------
#define BM 128
#define SWH 136                    // halves per smem row (128 + 8 pad)
#define SMEM_EMBED_BYTES (2 * 128 * SWH * 2)

// store a float4 (4 consecutive cols) as 4 halves at [row][c4..c4+3]
__device__ __forceinline__ void st_half4(__half* base, int row, int c4,
                                         float4 v) {
    __half2 p0 = __floats2half2_rn(v.x, v.y);
    __half2 p1 = __floats2half2_rn(v.z, v.w);
    uint2 u;
    u.x = *reinterpret_cast<uint32_t*>(&p0);
    u.y = *reinterpret_cast<uint32_t*>(&p1);
    *reinterpret_cast<uint2*>(base + row * SWH + c4) = u;
}

// one GEMM pass: acc[4][4][4] += A(sA, warp rows) * B(sW)   (K = 128)
__device__ __forceinline__ void compute_mma16(float acc[4][4][4],
                                              uint32_t sA32, uint32_t sW32,
                                              int wm, int wn, int lane) {
    const int quad = lane >> 3;        // 0..3 (8x8 matrix index for A x4)
    const int lr   = lane & 7;
    const int bk   = lane & 15;        // B k-row within 16-chunk
#pragma unroll
    for (int ks = 0; ks < 8; ks++) {
        uint32_t a[4][4];
#pragma unroll
        for (int mt = 0; mt < 4; mt++) {
            int arow = wm * 64 + mt * 16 + (quad & 1) * 8 + lr;
            int acol = ks * 16 + (quad >> 1) * 8;
            ldsm_x4(a[mt], sA32 + (arow * SWH + acol) * 2);
        }
#pragma unroll
        for (int nt = 0; nt < 4; nt++) {
            int brow = ks * 16 + bk;
            int bcol = wn * 32 + nt * 8;
            uint32_t b0, b1;
            ldsm_x2t(b0, b1, sW32 + (brow * SWH + bcol) * 2);
#pragma unroll
            for (int mt = 0; mt < 4; mt++)
                mma_f16(acc[mt][nt], a[mt][0], a[mt][1], a[mt][2], a[mt][3],
                        b0, b1);
        }
    }
}

__global__ __launch_bounds__(256) void embed_kernel(
    const float* __restrict__ s,
    const float* __restrict__ W1, const float* __restrict__ b1,
    const float* __restrict__ W2, const float* __restrict__ b2)
{
    extern __shared__ __half smem_h[];
    __half* sA = smem_h;               // 128 x SWH halves (input / h1)
    __half* sW = smem_h + 128 * SWH;   // 128 x SWH halves (weight K-tile)

    const uint32_t sA32 = (uint32_t)__cvta_generic_to_shared(sA);
    const uint32_t sW32 = (uint32_t)__cvta_generic_to_shared(sW);

    const int t    = threadIdx.x;
    const int r0   = blockIdx.x * BM;
    const int wid  = t >> 5, lane = t & 31;
    const int wm   = wid & 1, wn = wid >> 1;
    const int gid  = lane >> 2, tig = lane & 3;

    // ---- load s tile [128 x 128] (guarded, zero pad), fp16 ----
#pragma unroll
    for (int i = 0; i < 16; i++) {
        int idx4 = t + i * 256;
        int row  = idx4 >> 5;
        int c4   = (idx4 & 31) * 4;
        float4 val = make_float4(0.f, 0.f, 0.f, 0.f);
        if (r0 + row < N_NODES)
            val = *(const float4*)(s + (size_t)(r0 + row) * H + c4);
        st_half4(sA, row, c4, val);
    }
    // ---- load W1 [128 x 128], fp16 ----
#pragma unroll
    for (int i = 0; i < 16; i++) {
        int idx4 = t + i * 256;
        int row  = idx4 >> 5;
        int c4   = (idx4 & 31) * 4;
        st_half4(sW, row, c4, *(const float4*)(W1 + (size_t)row * H + c4));
    }
    __syncthreads();

    // ---- phase 1: acc = s @ W1 ----
    float acc[4][4][4];
#pragma unroll
    for (int mt = 0; mt < 4; mt++)
#pragma unroll
        for (int nt = 0; nt < 4; nt++)
#pragma unroll
            for (int i = 0; i < 4; i++) acc[mt][nt][i] = 0.f;

    compute_mma16(acc, sA32, sW32, wm, wn, lane);
    __syncthreads();   // all warps done reading sA/sW

    // ---- h1 = tanh(acc + b1) back into sA (fp16) ----
    // c0,c1 -> row (gid), cols 2tig,2tig+1 ; c2,c3 -> row+8
#pragma unroll
    for (int mt = 0; mt < 4; mt++) {
        int row = wm * 64 + mt * 16 + gid;
#pragma unroll
        for (int nt = 0; nt < 4; nt++) {
            int col = wn * 32 + nt * 8 + tig * 2;
            float ba = __ldg(b1 + col), bb = __ldg(b1 + col + 1);
            *(half2*)(sA + row * SWH + col) =
                __floats2half2_rn(tanhf(acc[mt][nt][0] + ba),
                                  tanhf(acc[mt][nt][1] + bb));
            *(half2*)(sA + (row + 8) * SWH + col) =
                __floats2half2_rn(tanhf(acc[mt][nt][2] + ba),
                                  tanhf(acc[mt][nt][3] + bb));
        }
    }

    // ---- phase 2: s_exp = h1 @ W2 + b2, 3 chunks of 128 cols, fp16 out ----
    for (int chunk = 0; chunk < 3; chunk++) {
        __syncthreads();   // h1 stores done / prev sW reads done
#pragma unroll
        for (int i = 0; i < 16; i++) {
            int idx4 = t + i * 256;
            int row  = idx4 >> 5;
            int c4   = (idx4 & 31) * 4;
            st_half4(sW, row, c4,
                     *(const float4*)(W2 + (size_t)row * H3 + chunk * 128 + c4));
        }
        __syncthreads();

        float acc2[4][4][4];
#pragma unroll
        for (int mt = 0; mt < 4; mt++)
#pragma unroll
            for (int nt = 0; nt < 4; nt++)
#pragma unroll
                for (int i = 0; i < 4; i++) acc2[mt][nt][i] = 0.f;

        compute_mma16(acc2, sA32, sW32, wm, wn, lane);

#pragma unroll
        for (int mt = 0; mt < 4; mt++) {
            int rl = wm * 64 + mt * 16 + gid;
#pragma unroll
            for (int nt = 0; nt < 4; nt++) {
                int col = chunk * 128 + wn * 32 + nt * 8 + tig * 2;
                float ba = __ldg(b2 + col), bb = __ldg(b2 + col + 1);
                int row = r0 + rl;
                if (row < N_NODES)
                    g_sexp16[(size_t)row * (H3 / 2) + (col >> 1)] =
                        __floats2half2_rn(acc2[mt][nt][0] + ba,
                                          acc2[mt][nt][1] + bb);
                if (row + 8 < N_NODES)
                    g_sexp16[(size_t)(row + 8) * (H3 / 2) + (col >> 1)] =
                        __floats2half2_rn(acc2[mt][nt][2] + ba,
                                          acc2[mt][nt][3] + bb);
            }
        }
    }
}

// ---------------------------------------------------------------------------
// v -> fp16 streaming conversion
// ---------------------------------------------------------------------------
__global__ __launch_bounds__(256) void vconv_kernel(const float* __restrict__ v) {
    size_t i = (size_t)blockIdx.x * 256 + threadIdx.x;
    const size_t n2 = (size_t)N_NODES * H3 / 2;
    if (i < n2) {
        float2 f = ((const float2*)v)[i];
        g_v16[i] = __floats2half2_rn(f.x, f.y);
    }
}

// ---------------------------------------------------------------------------
// CSR build: histogram -> two-level scan -> bucket fill (with payload)
// ---------------------------------------------------------------------------
__global__ __launch_bounds__(256) void hist_kernel(const int* __restrict__ ei) {
    int i = blockIdx.x * 256 + threadIdx.x;
    if (i < N_EDGES) atomicAdd(&g_count[__ldg(ei + N_EDGES + i)], 1);
}

__global__ __launch_bounds__(SCAN_B) void scan1_kernel() {
    __shared__ int red[SCAN_B / 32];
    const int idx = blockIdx.x * SCAN_B + threadIdx.x;
    int val = (idx < N_NODES) ? g_count[idx] : 0;
#pragma unroll
    for (int o = 16; o > 0; o >>= 1)
        val += __shfl_down_sync(0xffffffffu, val, o);
    if ((threadIdx.x & 31) == 0) red[threadIdx.x >> 5] = val;
    __syncthreads();
    if (threadIdx.x < SCAN_B / 32) {
        int v = red[threadIdx.x];
#pragma unroll
        for (int o = SCAN_B / 64; o > 0; o >>= 1)
            v += __shfl_down_sync(0xffu, v, o);
        if (threadIdx.x == 0) g_bsum[blockIdx.x] = v;
    }
}

__global__ __launch_bounds__(256) void scan2_kernel() {
    __shared__ int tmp[256];
    const int t = threadIdx.x;
    int v = (t < N_SBLK) ? g_bsum[t] : 0;
    tmp[t] = v;
    __syncthreads();
#pragma unroll
    for (int off = 1; off < 256; off <<= 1) {
        int u = (t >= off) ? tmp[t - off] : 0;
        __syncthreads();
        tmp[t] += u;
        __syncthreads();
    }
    if (t < N_SBLK) g_boff[t] = tmp[t] - v;   // exclusive
    if (t == 0) g_start[N_NODES] = N_EDGES;
}

__global__ __launch_bounds__(SCAN_B) void scan3_kernel() {
    __shared__ int tmp[SCAN_B];
    const int t = threadIdx.x;
    const int idx = blockIdx.x * SCAN_B + t;
    int v = (idx < N_NODES) ? g_count[idx] : 0;
    tmp[t] = v;
    __syncthreads();
#pragma unroll
    for (int off = 1; off < SCAN_B; off <<= 1) {
        int u = (t >= off) ? tmp[t - off] : 0;
        __syncthreads();
        tmp[t] += u;
        __syncthreads();
    }
    if (idx < N_NODES)
        g_start[idx] = g_boff[blockIdx.x] + tmp[t] - v;
}

__global__ __launch_bounds__(256) void fill_kernel(
    const int* __restrict__ ei,
    const float* __restrict__ dij,
    const float* __restrict__ dir)
{
    int e = blockIdx.x * 256 + threadIdx.x;
    if (e >= N_EDGES) return;
    int dst = __ldg(ei + N_EDGES + e);
    int pos = g_start[dst] + atomicAdd(&g_fill[dst], 1);
    g_bsrc[pos] = __ldg(ei + e);
    g_bdat[pos] = make_float4(__ldg(dij + e), __ldg(dir + 3 * e),
                              __ldg(dir + 3 * e + 1), __ldg(dir + 3 * e + 2));
}

// ---------------------------------------------------------------------------
// Kernel 2: gather + finalize. 128-thread block = 2 nodes x 64 threads.
// Thread owns half2 column pair c (cols 2c, 2c+1). fp32 accumulate.
// ---------------------------------------------------------------------------
__global__ __launch_bounds__(128) void gather_kernel(
    const float* __restrict__ v,
    const float* __restrict__ s,
    const float* __restrict__ Wd,
    const float* __restrict__ bd,
    float* __restrict__ out)
{
    const int t    = threadIdx.x;
    const int node = blockIdx.x * 2 + (t >> 6);
    const int c    = t & 63;                 // half2 column index, 0..63

    const int beg = g_start[node];
    const int end = g_start[node + 1];

    const float2 wv = *(const float2*)(Wd + 2 * c);
    const float2 bv = *(const float2*)(bd + 2 * c);
    const float2 ws = *(const float2*)(Wd + 128 + 2 * c);
    const float2 bs = *(const float2*)(bd + 128 + 2 * c);
    const float2 wr = *(const float2*)(Wd + 256 + 2 * c);
    const float2 br = *(const float2*)(bd + 256 + 2 * c);

    float2 accs = make_float2(0.f, 0.f);
    float2 a0 = accs, a1 = accs, a2 = accs;

#pragma unroll 4
    for (int j = beg; j < end; j++) {
        const int src = __ldg(g_bsrc + j);
        const float4 ed = __ldg(g_bdat + j);    // {d, d0, d1, d2}

        const __half2* sx = g_sexp16 + (size_t)src * 192;
        const float2 ev = __half22float2(__ldg(sx + c));
        const float2 es = __half22float2(__ldg(sx + 64 + c));
        const float2 er = __half22float2(__ldg(sx + 128 + c));

        const float gvx = ev.x * fmaf(ed.x, wv.x, bv.x);
        const float gvy = ev.y * fmaf(ed.x, wv.y, bv.y);
        const float grx = er.x * fmaf(ed.x, wr.x, br.x);
        const float gry = er.y * fmaf(ed.x, wr.y, br.y);

        accs.x = fmaf(es.x, fmaf(ed.x, ws.x, bs.x), accs.x);
        accs.y = fmaf(es.y, fmaf(ed.x, ws.y, bs.y), accs.y);

        const __half2* vb = g_v16 + (size_t)src * 192;
        const float2 v0 = __half22float2(__ldg(vb + c));
        const float2 v1 = __half22float2(__ldg(vb + 64 + c));
        const float2 v2 = __half22float2(__ldg(vb + 128 + c));

        a0.x = fmaf(grx, ed.y, fmaf(gvx, v0.x, a0.x));
        a0.y = fmaf(gry, ed.y, fmaf(gvy, v0.y, a0.y));
        a1.x = fmaf(grx, ed.z, fmaf(gvx, v1.x, a1.x));
        a1.y = fmaf(gry, ed.z, fmaf(gvy, v1.y, a1.y));
        a2.x = fmaf(grx, ed.w, fmaf(gvx, v2.x, a2.x));
        a2.y = fmaf(gry, ed.w, fmaf(gvy, v2.y, a2.y));
    }

    const float inv = 1.0f / fmaxf((float)(end - beg), 1.0f);

    const size_t vb = (size_t)node * H3;
    float2 o;
    float2 x0 = *(const float2*)(v + vb + 2 * c);
    o = make_float2(fmaf(a0.x, inv, x0.x), fmaf(a0.y, inv, x0.y));
    *(float2*)(out + vb + 2 * c) = o;
    float2 x1 = *(const float2*)(v + vb + 128 + 2 * c);
    o = make_float2(fmaf(a1.x, inv, x1.x), fmaf(a1.y, inv, x1.y));
    *(float2*)(out + vb + 128 + 2 * c) = o;
    float2 x2 = *(const float2*)(v + vb + 256 + 2 * c);
    o = make_float2(fmaf(a2.x, inv, x2.x), fmaf(a2.y, inv, x2.y));
    *(float2*)(out + vb + 256 + 2 * c) = o;

    float2 xs = *(const float2*)(s + (size_t)node * H + 2 * c);
    o = make_float2(fmaf(accs.x, inv, xs.x), fmaf(accs.y, inv, xs.y));
    *(float2*)(out + (size_t)N_NODES * H3 + (size_t)node * H + 2 * c) = o;
}

// ---------------------------------------------------------------------------
extern "C" void kernel_launch(void* const* d_in, const int* in_sizes, int n_in,
                              void* d_out, int out_size) {
    const float* v   = (const float*)d_in[0];
    const float* s   = (const float*)d_in[1];
    const int*   ei  = (const int*)  d_in[2];
    const float* dij = (const float*)d_in[3];
    const float* dir = (const float*)d_in[4];
    const float* W1  = (const float*)d_in[5];
    const float* b1  = (const float*)d_in[6];
    const float* W2  = (const float*)d_in[7];
    const float* b2  = (const float*)d_in[8];
    const float* Wd  = (const float*)d_in[9];
    const float* bd  = (const float*)d_in[10];
    float* out = (float*)d_out;

    cudaFuncSetAttribute(embed_kernel,
                         cudaFuncAttributeMaxDynamicSharedMemorySize,
                         SMEM_EMBED_BYTES);

    void *pcnt, *pfill;
    cudaGetSymbolAddress(&pcnt,  g_count);
    cudaGetSymbolAddress(&pfill, g_fill);
    cudaMemsetAsync(pcnt,  0, sizeof(int) * N_NODES, 0);
    cudaMemsetAsync(pfill, 0, sizeof(int) * N_NODES, 0);

    embed_kernel<<<(N_NODES + BM - 1) / BM, 256, SMEM_EMBED_BYTES>>>(
        s, W1, b1, W2, b2);
    vconv_kernel<<<(int)(((size_t)N_NODES * H3 / 2 + 255) / 256), 256>>>(v);
    hist_kernel<<<(N_EDGES + 255) / 256, 256>>>(ei);
    scan1_kernel<<<N_SBLK, SCAN_B>>>();
    scan2_kernel<<<1, 256>>>();
    scan3_kernel<<<N_SBLK, SCAN_B>>>();
    fill_kernel<<<(N_EDGES + 255) / 256, 256>>>(ei, dij, dir);
    gather_kernel<<<(N_NODES + 1) / 2, 128>>>(v, s, Wd, bd, out);
}

// round 13
// speedup vs baseline: 1.2211x; 1.0484x over previous
#include <cuda_runtime.h>
#include <cuda_fp16.h>
#include <cstdint>
#include <cstddef>

#define N_NODES 50000
#define N_EDGES 500000
#define H 128
#define H3 384
#define SCAN_B 256
#define N_SBLK ((N_NODES + SCAN_B - 1) / SCAN_B)   // 196

// ---------------- scratch (static device allocations, allowed) --------------
__device__ __half2 g_sexp16[(size_t)N_NODES * H3 / 2];  // 38.4 MB
__device__ __half2 g_v16  [(size_t)N_NODES * H3 / 2];   // 38.4 MB
__device__ int    g_count[N_NODES];
__device__ int    g_fill [N_NODES];
__device__ int    g_start[N_NODES + 1];
__device__ int    g_bsum [N_SBLK];
__device__ int    g_boff [N_SBLK];
__device__ int    g_bsrc [N_EDGES];                      // src per bucket slot
__device__ float4 g_bdat [N_EDGES];                      // {d, dir0, dir1, dir2}

// ---------------------------------------------------------------------------
// fp16 mma helpers (m16n8k16, fp32 accumulate) + ldmatrix
// ---------------------------------------------------------------------------
__device__ __forceinline__ void mma_f16(float c[4],
                                        uint32_t a0, uint32_t a1,
                                        uint32_t a2, uint32_t a3,
                                        uint32_t b0, uint32_t b1) {
    asm volatile(
        "mma.sync.aligned.m16n8k16.row.col.f32.f16.f16.f32 "
        "{%0,%1,%2,%3}, {%4,%5,%6,%7}, {%8,%9}, {%0,%1,%2,%3};"
        : "+f"(c[0]), "+f"(c[1]), "+f"(c[2]), "+f"(c[3])
        : "r"(a0), "r"(a1), "r"(a2), "r"(a3), "r"(b0), "r"(b1));
}

__device__ __forceinline__ void ldsm_x4(uint32_t r[4], uint32_t addr) {
    asm volatile("ldmatrix.sync.aligned.m8n8.x4.shared.b16 {%0,%1,%2,%3}, [%4];"
                 : "=r"(r[0]), "=r"(r[1]), "=r"(r[2]), "=r"(r[3]) : "r"(addr));
}

__device__ __forceinline__ void ldsm_x2t(uint32_t& b0, uint32_t& b1,
                                         uint32_t addr) {
    asm volatile("ldmatrix.sync.aligned.m8n8.x2.trans.shared.b16 {%0,%1}, [%2];"
                 : "=r"(b0), "=r"(b1) : "r"(addr));
}

// ---------------------------------------------------------------------------
// Kernel 1: s_exp = tanh(s @ W1 + b1) @ W2 + b2  -> fp16 g_sexp16  [N, 384]
// Block: 128 rows, 256 threads (8 warps: wm 0..1 x wn 0..3).
// Warp: 64 rows x 32 cols via 4x4 m16n8k16 fp16 mma tiles. 69.6 KB smem.
// ---------------------------------------------------------------------------
#define BM 128
#define SWH 136                    // halves per smem row (128 + 8 pad)
#define SMEM_EMBED_BYTES (2 * 128 * SWH * 2)

__device__ __forceinline__ void st_half4(__half* base, int row, int c4,
                                         float4 v) {
    __half2 p0 = __floats2half2_rn(v.x, v.y);
    __half2 p1 = __floats2half2_rn(v.z, v.w);
    uint2 u;
    u.x = *reinterpret_cast<uint32_t*>(&p0);
    u.y = *reinterpret_cast<uint32_t*>(&p1);
    *reinterpret_cast<uint2*>(base + row * SWH + c4) = u;
}

__device__ __forceinline__ void compute_mma16(float acc[4][4][4],
                                              uint32_t sA32, uint32_t sW32,
                                              int wm, int wn, int lane) {
    const int quad = lane >> 3;
    const int lr   = lane & 7;
    const int bk   = lane & 15;
#pragma unroll
    for (int ks = 0; ks < 8; ks++) {
        uint32_t a[4][4];
#pragma unroll
        for (int mt = 0; mt < 4; mt++) {
            int arow = wm * 64 + mt * 16 + (quad & 1) * 8 + lr;
            int acol = ks * 16 + (quad >> 1) * 8;
            ldsm_x4(a[mt], sA32 + (arow * SWH + acol) * 2);
        }
#pragma unroll
        for (int nt = 0; nt < 4; nt++) {
            int brow = ks * 16 + bk;
            int bcol = wn * 32 + nt * 8;
            uint32_t b0, b1;
            ldsm_x2t(b0, b1, sW32 + (brow * SWH + bcol) * 2);
#pragma unroll
            for (int mt = 0; mt < 4; mt++)
                mma_f16(acc[mt][nt], a[mt][0], a[mt][1], a[mt][2], a[mt][3],
                        b0, b1);
        }
    }
}

__global__ __launch_bounds__(256) void embed_kernel(
    const float* __restrict__ s,
    const float* __restrict__ W1, const float* __restrict__ b1,
    const float* __restrict__ W2, const float* __restrict__ b2)
{
    extern __shared__ __half smem_h[];
    __half* sA = smem_h;               // 128 x SWH halves (input / h1)
    __half* sW = smem_h + 128 * SWH;   // 128 x SWH halves (weight K-tile)

    const uint32_t sA32 = (uint32_t)__cvta_generic_to_shared(sA);
    const uint32_t sW32 = (uint32_t)__cvta_generic_to_shared(sW);

    const int t    = threadIdx.x;
    const int r0   = blockIdx.x * BM;
    const int wid  = t >> 5, lane = t & 31;
    const int wm   = wid & 1, wn = wid >> 1;
    const int gid  = lane >> 2, tig = lane & 3;

#pragma unroll
    for (int i = 0; i < 16; i++) {
        int idx4 = t + i * 256;
        int row  = idx4 >> 5;
        int c4   = (idx4 & 31) * 4;
        float4 val = make_float4(0.f, 0.f, 0.f, 0.f);
        if (r0 + row < N_NODES)
            val = *(const float4*)(s + (size_t)(r0 + row) * H + c4);
        st_half4(sA, row, c4, val);
    }
#pragma unroll
    for (int i = 0; i < 16; i++) {
        int idx4 = t + i * 256;
        int row  = idx4 >> 5;
        int c4   = (idx4 & 31) * 4;
        st_half4(sW, row, c4, *(const float4*)(W1 + (size_t)row * H + c4));
    }
    __syncthreads();

    float acc[4][4][4];
#pragma unroll
    for (int mt = 0; mt < 4; mt++)
#pragma unroll
        for (int nt = 0; nt < 4; nt++)
#pragma unroll
            for (int i = 0; i < 4; i++) acc[mt][nt][i] = 0.f;

    compute_mma16(acc, sA32, sW32, wm, wn, lane);
    __syncthreads();

#pragma unroll
    for (int mt = 0; mt < 4; mt++) {
        int row = wm * 64 + mt * 16 + gid;
#pragma unroll
        for (int nt = 0; nt < 4; nt++) {
            int col = wn * 32 + nt * 8 + tig * 2;
            float ba = __ldg(b1 + col), bb = __ldg(b1 + col + 1);
            *(half2*)(sA + row * SWH + col) =
                __floats2half2_rn(tanhf(acc[mt][nt][0] + ba),
                                  tanhf(acc[mt][nt][1] + bb));
            *(half2*)(sA + (row + 8) * SWH + col) =
                __floats2half2_rn(tanhf(acc[mt][nt][2] + ba),
                                  tanhf(acc[mt][nt][3] + bb));
        }
    }

    for (int chunk = 0; chunk < 3; chunk++) {
        __syncthreads();
#pragma unroll
        for (int i = 0; i < 16; i++) {
            int idx4 = t + i * 256;
            int row  = idx4 >> 5;
            int c4   = (idx4 & 31) * 4;
            st_half4(sW, row, c4,
                     *(const float4*)(W2 + (size_t)row * H3 + chunk * 128 + c4));
        }
        __syncthreads();

        float acc2[4][4][4];
#pragma unroll
        for (int mt = 0; mt < 4; mt++)
#pragma unroll
            for (int nt = 0; nt < 4; nt++)
#pragma unroll
                for (int i = 0; i < 4; i++) acc2[mt][nt][i] = 0.f;

        compute_mma16(acc2, sA32, sW32, wm, wn, lane);

#pragma unroll
        for (int mt = 0; mt < 4; mt++) {
            int rl = wm * 64 + mt * 16 + gid;
#pragma unroll
            for (int nt = 0; nt < 4; nt++) {
                int col = chunk * 128 + wn * 32 + nt * 8 + tig * 2;
                float ba = __ldg(b2 + col), bb = __ldg(b2 + col + 1);
                int row = r0 + rl;
                if (row < N_NODES)
                    g_sexp16[(size_t)row * (H3 / 2) + (col >> 1)] =
                        __floats2half2_rn(acc2[mt][nt][0] + ba,
                                          acc2[mt][nt][1] + bb);
                if (row + 8 < N_NODES)
                    g_sexp16[(size_t)(row + 8) * (H3 / 2) + (col >> 1)] =
                        __floats2half2_rn(acc2[mt][nt][2] + ba,
                                          acc2[mt][nt][3] + bb);
            }
        }
    }
}

// ---------------------------------------------------------------------------
// v -> fp16 streaming conversion
// ---------------------------------------------------------------------------
__global__ __launch_bounds__(256) void vconv_kernel(const float* __restrict__ v) {
    size_t i = (size_t)blockIdx.x * 256 + threadIdx.x;
    const size_t n2 = (size_t)N_NODES * H3 / 2;
    if (i < n2) {
        float2 f = ((const float2*)v)[i];
        g_v16[i] = __floats2half2_rn(f.x, f.y);
    }
}

// ---------------------------------------------------------------------------
// CSR build: histogram -> two-level scan -> bucket fill (with payload)
// ---------------------------------------------------------------------------
__global__ __launch_bounds__(256) void hist_kernel(const int* __restrict__ ei) {
    int i = blockIdx.x * 256 + threadIdx.x;
    if (i < N_EDGES) atomicAdd(&g_count[__ldg(ei + N_EDGES + i)], 1);
}

__global__ __launch_bounds__(SCAN_B) void scan1_kernel() {
    __shared__ int red[SCAN_B / 32];
    const int idx = blockIdx.x * SCAN_B + threadIdx.x;
    int val = (idx < N_NODES) ? g_count[idx] : 0;
#pragma unroll
    for (int o = 16; o > 0; o >>= 1)
        val += __shfl_down_sync(0xffffffffu, val, o);
    if ((threadIdx.x & 31) == 0) red[threadIdx.x >> 5] = val;
    __syncthreads();
    if (threadIdx.x < SCAN_B / 32) {
        int v = red[threadIdx.x];
#pragma unroll
        for (int o = SCAN_B / 64; o > 0; o >>= 1)
            v += __shfl_down_sync(0xffu, v, o);
        if (threadIdx.x == 0) g_bsum[blockIdx.x] = v;
    }
}

__global__ __launch_bounds__(256) void scan2_kernel() {
    __shared__ int tmp[256];
    const int t = threadIdx.x;
    int v = (t < N_SBLK) ? g_bsum[t] : 0;
    tmp[t] = v;
    __syncthreads();
#pragma unroll
    for (int off = 1; off < 256; off <<= 1) {
        int u = (t >= off) ? tmp[t - off] : 0;
        __syncthreads();
        tmp[t] += u;
        __syncthreads();
    }
    if (t < N_SBLK) g_boff[t] = tmp[t] - v;   // exclusive
    if (t == 0) g_start[N_NODES] = N_EDGES;
}

__global__ __launch_bounds__(SCAN_B) void scan3_kernel() {
    __shared__ int tmp[SCAN_B];
    const int t = threadIdx.x;
    const int idx = blockIdx.x * SCAN_B + t;
    int v = (idx < N_NODES) ? g_count[idx] : 0;
    tmp[t] = v;
    __syncthreads();
#pragma unroll
    for (int off = 1; off < SCAN_B; off <<= 1) {
        int u = (t >= off) ? tmp[t - off] : 0;
        __syncthreads();
        tmp[t] += u;
        __syncthreads();
    }
    if (idx < N_NODES)
        g_start[idx] = g_boff[blockIdx.x] + tmp[t] - v;
}

__global__ __launch_bounds__(256) void fill_kernel(
    const int* __restrict__ ei,
    const float* __restrict__ dij,
    const float* __restrict__ dir)
{
    int e = blockIdx.x * 256 + threadIdx.x;
    if (e >= N_EDGES) return;
    int dst = __ldg(ei + N_EDGES + e);
    int pos = g_start[dst] + atomicAdd(&g_fill[dst], 1);
    g_bsrc[pos] = __ldg(ei + e);
    g_bdat[pos] = make_float4(__ldg(dij + e), __ldg(dir + 3 * e),
                              __ldg(dir + 3 * e + 1), __ldg(dir + 3 * e + 2));
}

// ---------------------------------------------------------------------------
// Kernel 2: gather + finalize. 128-thread block = 2 nodes x 64 threads.
// ---------------------------------------------------------------------------
__global__ __launch_bounds__(128) void gather_kernel(
    const float* __restrict__ v,
    const float* __restrict__ s,
    const float* __restrict__ Wd,
    const float* __restrict__ bd,
    float* __restrict__ out)
{
    const int t    = threadIdx.x;
    const int node = blockIdx.x * 2 + (t >> 6);
    const int c    = t & 63;                 // half2 column index, 0..63

    const int beg = g_start[node];
    const int end = g_start[node + 1];

    const float2 wv = *(const float2*)(Wd + 2 * c);
    const float2 bv = *(const float2*)(bd + 2 * c);
    const float2 ws = *(const float2*)(Wd + 128 + 2 * c);
    const float2 bs = *(const float2*)(bd + 128 + 2 * c);
    const float2 wr = *(const float2*)(Wd + 256 + 2 * c);
    const float2 br = *(const float2*)(bd + 256 + 2 * c);

    float2 accs = make_float2(0.f, 0.f);
    float2 a0 = accs, a1 = accs, a2 = accs;

#pragma unroll 4
    for (int j = beg; j < end; j++) {
        const int src = __ldg(g_bsrc + j);
        const float4 ed = __ldg(g_bdat + j);    // {d, d0, d1, d2}

        const __half2* sx = g_sexp16 + (size_t)src * 192;
        const float2 ev = __half22float2(__ldg(sx + c));
        const float2 es = __half22float2(__ldg(sx + 64 + c));
        const float2 er = __half22float2(__ldg(sx + 128 + c));

        const float gvx = ev.x * fmaf(ed.x, wv.x, bv.x);
        const float gvy = ev.y * fmaf(ed.x, wv.y, bv.y);
        const float grx = er.x * fmaf(ed.x, wr.x, br.x);
        const float gry = er.y * fmaf(ed.x, wr.y, br.y);

        accs.x = fmaf(es.x, fmaf(ed.x, ws.x, bs.x), accs.x);
        accs.y = fmaf(es.y, fmaf(ed.x, ws.y, bs.y), accs.y);

        const __half2* vb = g_v16 + (size_t)src * 192;
        const float2 v0 = __half22float2(__ldg(vb + c));
        const float2 v1 = __half22float2(__ldg(vb + 64 + c));
        const float2 v2 = __half22float2(__ldg(vb + 128 + c));

        a0.x = fmaf(grx, ed.y, fmaf(gvx, v0.x, a0.x));
        a0.y = fmaf(gry, ed.y, fmaf(gvy, v0.y, a0.y));
        a1.x = fmaf(grx, ed.z, fmaf(gvx, v1.x, a1.x));
        a1.y = fmaf(gry, ed.z, fmaf(gvy, v1.y, a1.y));
        a2.x = fmaf(grx, ed.w, fmaf(gvx, v2.x, a2.x));
        a2.y = fmaf(gry, ed.w, fmaf(gvy, v2.y, a2.y));
    }

    const float inv = 1.0f / fmaxf((float)(end - beg), 1.0f);

    const size_t vb = (size_t)node * H3;
    float2 o;
    float2 x0 = *(const float2*)(v + vb + 2 * c);
    o = make_float2(fmaf(a0.x, inv, x0.x), fmaf(a0.y, inv, x0.y));
    *(float2*)(out + vb + 2 * c) = o;
    float2 x1 = *(const float2*)(v + vb + 128 + 2 * c);
    o = make_float2(fmaf(a1.x, inv, x1.x), fmaf(a1.y, inv, x1.y));
    *(float2*)(out + vb + 128 + 2 * c) = o;
    float2 x2 = *(const float2*)(v + vb + 256 + 2 * c);
    o = make_float2(fmaf(a2.x, inv, x2.x), fmaf(a2.y, inv, x2.y));
    *(float2*)(out + vb + 256 + 2 * c) = o;

    float2 xs = *(const float2*)(s + (size_t)node * H + 2 * c);
    o = make_float2(fmaf(accs.x, inv, xs.x), fmaf(accs.y, inv, xs.y));
    *(float2*)(out + (size_t)N_NODES * H3 + (size_t)node * H + 2 * c) = o;
}

// ---------------------------------------------------------------------------
// Launch: three independent chains overlapped via multi-stream graph capture.
//   chain A (stream 0): embed
//   chain B (sB):       vconv
//   chain C (sC):       memsets -> hist -> scan1/2/3 -> fill
// join -> gather on stream 0.
// Streams/events are created lazily on the first (uncaptured) call and reused.
// ---------------------------------------------------------------------------
extern "C" void kernel_launch(void* const* d_in, const int* in_sizes, int n_in,
                              void* d_out, int out_size) {
    const float* v   = (const float*)d_in[0];
    const float* s   = (const float*)d_in[1];
    const int*   ei  = (const int*)  d_in[2];
    const float* dij = (const float*)d_in[3];
    const float* dir = (const float*)d_in[4];
    const float* W1  = (const float*)d_in[5];
    const float* b1  = (const float*)d_in[6];
    const float* W2  = (const float*)d_in[7];
    const float* b2  = (const float*)d_in[8];
    const float* Wd  = (const float*)d_in[9];
    const float* bd  = (const float*)d_in[10];
    float* out = (float*)d_out;

    static cudaStream_t sB = nullptr, sC = nullptr;
    static cudaEvent_t  eFork = nullptr, eJoinB = nullptr, eJoinC = nullptr;
    if (sB == nullptr) {
        cudaStreamCreateWithFlags(&sB, cudaStreamNonBlocking);
        cudaStreamCreateWithFlags(&sC, cudaStreamNonBlocking);
        cudaEventCreateWithFlags(&eFork,  cudaEventDisableTiming);
        cudaEventCreateWithFlags(&eJoinB, cudaEventDisableTiming);
        cudaEventCreateWithFlags(&eJoinC, cudaEventDisableTiming);
        cudaFuncSetAttribute(embed_kernel,
                             cudaFuncAttributeMaxDynamicSharedMemorySize,
                             SMEM_EMBED_BYTES);
    }

    void *pcnt, *pfill;
    cudaGetSymbolAddress(&pcnt,  g_count);
    cudaGetSymbolAddress(&pfill, g_fill);

    // fork side streams off the capture-origin stream
    cudaEventRecord(eFork, 0);
    cudaStreamWaitEvent(sB, eFork, 0);
    cudaStreamWaitEvent(sC, eFork, 0);

    // chain C: CSR build
    cudaMemsetAsync(pcnt,  0, sizeof(int) * N_NODES, sC);
    cudaMemsetAsync(pfill, 0, sizeof(int) * N_NODES, sC);
    hist_kernel<<<(N_EDGES + 255) / 256, 256, 0, sC>>>(ei);
    scan1_kernel<<<N_SBLK, SCAN_B, 0, sC>>>();
    scan2_kernel<<<1, 256, 0, sC>>>();
    scan3_kernel<<<N_SBLK, SCAN_B, 0, sC>>>();
    fill_kernel<<<(N_EDGES + 255) / 256, 256, 0, sC>>>(ei, dij, dir);

    // chain B: v -> fp16
    vconv_kernel<<<(int)(((size_t)N_NODES * H3 / 2 + 255) / 256), 256, 0, sB>>>(v);

    // chain A: embed MLP (capture-origin stream)
    embed_kernel<<<(N_NODES + BM - 1) / BM, 256, SMEM_EMBED_BYTES>>>(
        s, W1, b1, W2, b2);

    // join
    cudaEventRecord(eJoinB, sB);
    cudaEventRecord(eJoinC, sC);
    cudaStreamWaitEvent(0, eJoinB, 0);
    cudaStreamWaitEvent(0, eJoinC, 0);

    gather_kernel<<<(N_NODES + 1) / 2, 128>>>(v, s, Wd, bd, out);
}

// round 14
// speedup vs baseline: 1.2247x; 1.0030x over previous
#include <cuda_runtime.h>
#include <cuda_fp16.h>
#include <cstdint>
#include <cstddef>

#define N_NODES 50000
#define N_EDGES 500000
#define H 128
#define H3 384
#define SCAN_B 256
#define N_SBLK ((N_NODES + SCAN_B - 1) / SCAN_B)   // 196

// ---------------- scratch (static device allocations, allowed) --------------
// packed per-node gather row: [es(128h) | er(128h) | q0(3*128h)] = 640 halves
// q0[a,k] = ev[k] * v[node,a,k]
#define PACK_H2 320
__device__ __half2 g_pack[(size_t)N_NODES * PACK_H2];   // 64 MB
__device__ int    g_count[N_NODES];
__device__ int    g_fill [N_NODES];
__device__ int    g_start[N_NODES + 1];
__device__ int    g_bsum [N_SBLK];
__device__ int    g_boff [N_SBLK];
__device__ int    g_bsrc [N_EDGES];
__device__ float4 g_bdat [N_EDGES];                      // {d, dir0, dir1, dir2}

// ---------------------------------------------------------------------------
// fp16 mma helpers (m16n8k16, fp32 accumulate) + ldmatrix
// ---------------------------------------------------------------------------
__device__ __forceinline__ void mma_f16(float c[4],
                                        uint32_t a0, uint32_t a1,
                                        uint32_t a2, uint32_t a3,
                                        uint32_t b0, uint32_t b1) {
    asm volatile(
        "mma.sync.aligned.m16n8k16.row.col.f32.f16.f16.f32 "
        "{%0,%1,%2,%3}, {%4,%5,%6,%7}, {%8,%9}, {%0,%1,%2,%3};"
        : "+f"(c[0]), "+f"(c[1]), "+f"(c[2]), "+f"(c[3])
        : "r"(a0), "r"(a1), "r"(a2), "r"(a3), "r"(b0), "r"(b1));
}

__device__ __forceinline__ void ldsm_x4(uint32_t r[4], uint32_t addr) {
    asm volatile("ldmatrix.sync.aligned.m8n8.x4.shared.b16 {%0,%1,%2,%3}, [%4];"
                 : "=r"(r[0]), "=r"(r[1]), "=r"(r[2]), "=r"(r[3]) : "r"(addr));
}

__device__ __forceinline__ void ldsm_x2t(uint32_t& b0, uint32_t& b1,
                                         uint32_t addr) {
    asm volatile("ldmatrix.sync.aligned.m8n8.x2.trans.shared.b16 {%0,%1}, [%2];"
                 : "=r"(b0), "=r"(b1) : "r"(addr));
}

// ---------------------------------------------------------------------------
// Kernel 1: s_exp = tanh(s @ W1 + b1) @ W2 + b2, fused epilogue packs
//   chunk0 (ev cols 0..127)   -> q0[a] = ev * v[row,a,:]  (pack offs 256..639)
//   chunk1 (es cols 128..255) -> pack offs 0..127
//   chunk2 (er cols 256..383) -> pack offs 128..255
// ---------------------------------------------------------------------------
#define BM 128
#define SWH 136
#define SMEM_EMBED_BYTES (2 * 128 * SWH * 2)

__device__ __forceinline__ void st_half4(__half* base, int row, int c4,
                                         float4 v) {
    __half2 p0 = __floats2half2_rn(v.x, v.y);
    __half2 p1 = __floats2half2_rn(v.z, v.w);
    uint2 u;
    u.x = *reinterpret_cast<uint32_t*>(&p0);
    u.y = *reinterpret_cast<uint32_t*>(&p1);
    *reinterpret_cast<uint2*>(base + row * SWH + c4) = u;
}

__device__ __forceinline__ void compute_mma16(float acc[4][4][4],
                                              uint32_t sA32, uint32_t sW32,
                                              int wm, int wn, int lane) {
    const int quad = lane >> 3;
    const int lr   = lane & 7;
    const int bk   = lane & 15;
#pragma unroll
    for (int ks = 0; ks < 8; ks++) {
        uint32_t a[4][4];
#pragma unroll
        for (int mt = 0; mt < 4; mt++) {
            int arow = wm * 64 + mt * 16 + (quad & 1) * 8 + lr;
            int acol = ks * 16 + (quad >> 1) * 8;
            ldsm_x4(a[mt], sA32 + (arow * SWH + acol) * 2);
        }
#pragma unroll
        for (int nt = 0; nt < 4; nt++) {
            int brow = ks * 16 + bk;
            int bcol = wn * 32 + nt * 8;
            uint32_t b0, b1;
            ldsm_x2t(b0, b1, sW32 + (brow * SWH + bcol) * 2);
#pragma unroll
            for (int mt = 0; mt < 4; mt++)
                mma_f16(acc[mt][nt], a[mt][0], a[mt][1], a[mt][2], a[mt][3],
                        b0, b1);
        }
    }
}

// write one (row, col-pair) result into the packed layout
__device__ __forceinline__ void pack_store(int row, int chunk, int col,
                                           float r0, float r1,
                                           const float* __restrict__ v) {
    if (row >= N_NODES) return;
    __half2* pr = g_pack + (size_t)row * PACK_H2;
    if (chunk == 0) {
        // q0[a] = ev * v[row, a, col..col+1]
#pragma unroll
        for (int a = 0; a < 3; a++) {
            float2 vv = *(const float2*)(v + (size_t)row * H3 + a * H + col);
            pr[128 + a * 64 + (col >> 1)] =
                __floats2half2_rn(r0 * vv.x, r1 * vv.y);
        }
    } else if (chunk == 1) {
        pr[(col - 128) >> 1] = __floats2half2_rn(r0, r1);       // es
    } else {
        pr[64 + ((col - 256) >> 1)] = __floats2half2_rn(r0, r1); // er
    }
}

__global__ __launch_bounds__(256) void embed_kernel(
    const float* __restrict__ s,
    const float* __restrict__ v,
    const float* __restrict__ W1, const float* __restrict__ b1,
    const float* __restrict__ W2, const float* __restrict__ b2)
{
    extern __shared__ __half smem_h[];
    __half* sA = smem_h;
    __half* sW = smem_h + 128 * SWH;

    const uint32_t sA32 = (uint32_t)__cvta_generic_to_shared(sA);
    const uint32_t sW32 = (uint32_t)__cvta_generic_to_shared(sW);

    const int t    = threadIdx.x;
    const int r0   = blockIdx.x * BM;
    const int wid  = t >> 5, lane = t & 31;
    const int wm   = wid & 1, wn = wid >> 1;
    const int gid  = lane >> 2, tig = lane & 3;

#pragma unroll
    for (int i = 0; i < 16; i++) {
        int idx4 = t + i * 256;
        int row  = idx4 >> 5;
        int c4   = (idx4 & 31) * 4;
        float4 val = make_float4(0.f, 0.f, 0.f, 0.f);
        if (r0 + row < N_NODES)
            val = *(const float4*)(s + (size_t)(r0 + row) * H + c4);
        st_half4(sA, row, c4, val);
    }
#pragma unroll
    for (int i = 0; i < 16; i++) {
        int idx4 = t + i * 256;
        int row  = idx4 >> 5;
        int c4   = (idx4 & 31) * 4;
        st_half4(sW, row, c4, *(const float4*)(W1 + (size_t)row * H + c4));
    }
    __syncthreads();

    float acc[4][4][4];
#pragma unroll
    for (int mt = 0; mt < 4; mt++)
#pragma unroll
        for (int nt = 0; nt < 4; nt++)
#pragma unroll
            for (int i = 0; i < 4; i++) acc[mt][nt][i] = 0.f;

    compute_mma16(acc, sA32, sW32, wm, wn, lane);
    __syncthreads();

#pragma unroll
    for (int mt = 0; mt < 4; mt++) {
        int row = wm * 64 + mt * 16 + gid;
#pragma unroll
        for (int nt = 0; nt < 4; nt++) {
            int col = wn * 32 + nt * 8 + tig * 2;
            float ba = __ldg(b1 + col), bb = __ldg(b1 + col + 1);
            *(half2*)(sA + row * SWH + col) =
                __floats2half2_rn(tanhf(acc[mt][nt][0] + ba),
                                  tanhf(acc[mt][nt][1] + bb));
            *(half2*)(sA + (row + 8) * SWH + col) =
                __floats2half2_rn(tanhf(acc[mt][nt][2] + ba),
                                  tanhf(acc[mt][nt][3] + bb));
        }
    }

    for (int chunk = 0; chunk < 3; chunk++) {
        __syncthreads();
#pragma unroll
        for (int i = 0; i < 16; i++) {
            int idx4 = t + i * 256;
            int row  = idx4 >> 5;
            int c4   = (idx4 & 31) * 4;
            st_half4(sW, row, c4,
                     *(const float4*)(W2 + (size_t)row * H3 + chunk * 128 + c4));
        }
        __syncthreads();

        float acc2[4][4][4];
#pragma unroll
        for (int mt = 0; mt < 4; mt++)
#pragma unroll
            for (int nt = 0; nt < 4; nt++)
#pragma unroll
                for (int i = 0; i < 4; i++) acc2[mt][nt][i] = 0.f;

        compute_mma16(acc2, sA32, sW32, wm, wn, lane);

#pragma unroll
        for (int mt = 0; mt < 4; mt++) {
            int rl = wm * 64 + mt * 16 + gid;
#pragma unroll
            for (int nt = 0; nt < 4; nt++) {
                int col = chunk * 128 + wn * 32 + nt * 8 + tig * 2;
                float ba = __ldg(b2 + col), bb = __ldg(b2 + col + 1);
                int lcol = col - chunk * 128;  // 0..127 within chunk
                pack_store(r0 + rl, chunk, chunk ? col : lcol,
                           acc2[mt][nt][0] + ba, acc2[mt][nt][1] + bb, v);
                pack_store(r0 + rl + 8, chunk, chunk ? col : lcol,
                           acc2[mt][nt][2] + ba, acc2[mt][nt][3] + bb, v);
            }
        }
    }
}

// ---------------------------------------------------------------------------
// CSR build: histogram -> two-level scan -> bucket fill (with payload)
// ---------------------------------------------------------------------------
__global__ __launch_bounds__(256) void hist_kernel(const int* __restrict__ ei) {
    int i = blockIdx.x * 256 + threadIdx.x;
    if (i < N_EDGES) atomicAdd(&g_count[__ldg(ei + N_EDGES + i)], 1);
}

__global__ __launch_bounds__(SCAN_B) void scan1_kernel() {
    __shared__ int red[SCAN_B / 32];
    const int idx = blockIdx.x * SCAN_B + threadIdx.x;
    int val = (idx < N_NODES) ? g_count[idx] : 0;
#pragma unroll
    for (int o = 16; o > 0; o >>= 1)
        val += __shfl_down_sync(0xffffffffu, val, o);
    if ((threadIdx.x & 31) == 0) red[threadIdx.x >> 5] = val;
    __syncthreads();
    if (threadIdx.x < SCAN_B / 32) {
        int v = red[threadIdx.x];
#pragma unroll
        for (int o = SCAN_B / 64; o > 0; o >>= 1)
            v += __shfl_down_sync(0xffu, v, o);
        if (threadIdx.x == 0) g_bsum[blockIdx.x] = v;
    }
}

__global__ __launch_bounds__(256) void scan2_kernel() {
    __shared__ int tmp[256];
    const int t = threadIdx.x;
    int v = (t < N_SBLK) ? g_bsum[t] : 0;
    tmp[t] = v;
    __syncthreads();
#pragma unroll
    for (int off = 1; off < 256; off <<= 1) {
        int u = (t >= off) ? tmp[t - off] : 0;
        __syncthreads();
        tmp[t] += u;
        __syncthreads();
    }
    if (t < N_SBLK) g_boff[t] = tmp[t] - v;   // exclusive
    if (t == 0) g_start[N_NODES] = N_EDGES;
}

__global__ __launch_bounds__(SCAN_B) void scan3_kernel() {
    __shared__ int tmp[SCAN_B];
    const int t = threadIdx.x;
    const int idx = blockIdx.x * SCAN_B + t;
    int v = (idx < N_NODES) ? g_count[idx] : 0;
    tmp[t] = v;
    __syncthreads();
#pragma unroll
    for (int off = 1; off < SCAN_B; off <<= 1) {
        int u = (t >= off) ? tmp[t - off] : 0;
        __syncthreads();
        tmp[t] += u;
        __syncthreads();
    }
    if (idx < N_NODES)
        g_start[idx] = g_boff[blockIdx.x] + tmp[t] - v;
}

__global__ __launch_bounds__(256) void fill_kernel(
    const int* __restrict__ ei,
    const float* __restrict__ dij,
    const float* __restrict__ dir)
{
    int e = blockIdx.x * 256 + threadIdx.x;
    if (e >= N_EDGES) return;
    int dst = __ldg(ei + N_EDGES + e);
    int pos = g_start[dst] + atomicAdd(&g_fill[dst], 1);
    g_bsrc[pos] = __ldg(ei + e);
    g_bdat[pos] = make_float4(__ldg(dij + e), __ldg(dir + 3 * e),
                              __ldg(dir + 3 * e + 1), __ldg(dir + 3 * e + 2));
}

// ---------------------------------------------------------------------------
// Kernel 2: gather + finalize. 128-thread block = 2 nodes x 64 threads.
// 5 packed gathers per edge: es, er, q0[0..2].
//   ds  += es * (bs + d*ws)
//   dv_a += er*(br + d*wr)*dir_a + (bv + d*wv)*q0_a
// ---------------------------------------------------------------------------
__global__ __launch_bounds__(128) void gather_kernel(
    const float* __restrict__ v,
    const float* __restrict__ s,
    const float* __restrict__ Wd,
    const float* __restrict__ bd,
    float* __restrict__ out)
{
    const int t    = threadIdx.x;
    const int node = blockIdx.x * 2 + (t >> 6);
    const int c    = t & 63;                 // half2 column index, 0..63

    const int beg = g_start[node];
    const int end = g_start[node + 1];

    const float2 wv = *(const float2*)(Wd + 2 * c);
    const float2 bv = *(const float2*)(bd + 2 * c);
    const float2 ws = *(const float2*)(Wd + 128 + 2 * c);
    const float2 bs = *(const float2*)(bd + 128 + 2 * c);
    const float2 wr = *(const float2*)(Wd + 256 + 2 * c);
    const float2 br = *(const float2*)(bd + 256 + 2 * c);

    float2 accs = make_float2(0.f, 0.f);
    float2 a0 = accs, a1 = accs, a2 = accs;

#pragma unroll 4
    for (int j = beg; j < end; j++) {
        const int src = __ldg(g_bsrc + j);
        const float4 ed = __ldg(g_bdat + j);    // {d, d0, d1, d2}

        const __half2* pr = g_pack + (size_t)src * PACK_H2;
        const float2 es = __half22float2(__ldg(pr + c));
        const float2 er = __half22float2(__ldg(pr + 64 + c));
        const float2 q0 = __half22float2(__ldg(pr + 128 + c));
        const float2 q1 = __half22float2(__ldg(pr + 192 + c));
        const float2 q2 = __half22float2(__ldg(pr + 256 + c));

        const float gqx = fmaf(ed.x, wv.x, bv.x);   // dv_v weight
        const float gqy = fmaf(ed.x, wv.y, bv.y);
        const float grx = er.x * fmaf(ed.x, wr.x, br.x);
        const float gry = er.y * fmaf(ed.x, wr.y, br.y);

        accs.x = fmaf(es.x, fmaf(ed.x, ws.x, bs.x), accs.x);
        accs.y = fmaf(es.y, fmaf(ed.x, ws.y, bs.y), accs.y);

        a0.x = fmaf(grx, ed.y, fmaf(gqx, q0.x, a0.x));
        a0.y = fmaf(gry, ed.y, fmaf(gqy, q0.y, a0.y));
        a1.x = fmaf(grx, ed.z, fmaf(gqx, q1.x, a1.x));
        a1.y = fmaf(gry, ed.z, fmaf(gqy, q1.y, a1.y));
        a2.x = fmaf(grx, ed.w, fmaf(gqx, q2.x, a2.x));
        a2.y = fmaf(gry, ed.w, fmaf(gqy, q2.y, a2.y));
    }

    const float inv = 1.0f / fmaxf((float)(end - beg), 1.0f);

    const size_t vb = (size_t)node * H3;
    float2 o;
    float2 x0 = *(const float2*)(v + vb + 2 * c);
    o = make_float2(fmaf(a0.x, inv, x0.x), fmaf(a0.y, inv, x0.y));
    *(float2*)(out + vb + 2 * c) = o;
    float2 x1 = *(const float2*)(v + vb + 128 + 2 * c);
    o = make_float2(fmaf(a1.x, inv, x1.x), fmaf(a1.y, inv, x1.y));
    *(float2*)(out + vb + 128 + 2 * c) = o;
    float2 x2 = *(const float2*)(v + vb + 256 + 2 * c);
    o = make_float2(fmaf(a2.x, inv, x2.x), fmaf(a2.y, inv, x2.y));
    *(float2*)(out + vb + 256 + 2 * c) = o;

    float2 xs = *(const float2*)(s + (size_t)node * H + 2 * c);
    o = make_float2(fmaf(accs.x, inv, xs.x), fmaf(accs.y, inv, xs.y));
    *(float2*)(out + (size_t)N_NODES * H3 + (size_t)node * H + 2 * c) = o;
}

// ---------------------------------------------------------------------------
// Launch: two independent chains overlapped via multi-stream graph capture.
//   chain A (stream 0): embed (incl. q0 pack)
//   chain C (sC):       memsets -> hist -> scan1/2/3 -> fill
// join -> gather on stream 0.
// ---------------------------------------------------------------------------
extern "C" void kernel_launch(void* const* d_in, const int* in_sizes, int n_in,
                              void* d_out, int out_size) {
    const float* v   = (const float*)d_in[0];
    const float* s   = (const float*)d_in[1];
    const int*   ei  = (const int*)  d_in[2];
    const float* dij = (const float*)d_in[3];
    const float* dir = (const float*)d_in[4];
    const float* W1  = (const float*)d_in[5];
    const float* b1  = (const float*)d_in[6];
    const float* W2  = (const float*)d_in[7];
    const float* b2  = (const float*)d_in[8];
    const float* Wd  = (const float*)d_in[9];
    const float* bd  = (const float*)d_in[10];
    float* out = (float*)d_out;

    static cudaStream_t sC = nullptr;
    static cudaEvent_t  eFork = nullptr, eJoinC = nullptr;
    if (sC == nullptr) {
        cudaStreamCreateWithFlags(&sC, cudaStreamNonBlocking);
        cudaEventCreateWithFlags(&eFork,  cudaEventDisableTiming);
        cudaEventCreateWithFlags(&eJoinC, cudaEventDisableTiming);
        cudaFuncSetAttribute(embed_kernel,
                             cudaFuncAttributeMaxDynamicSharedMemorySize,
                             SMEM_EMBED_BYTES);
    }

    void *pcnt, *pfill;
    cudaGetSymbolAddress(&pcnt,  g_count);
    cudaGetSymbolAddress(&pfill, g_fill);

    cudaEventRecord(eFork, 0);
    cudaStreamWaitEvent(sC, eFork, 0);

    // chain C: CSR build
    cudaMemsetAsync(pcnt,  0, sizeof(int) * N_NODES, sC);
    cudaMemsetAsync(pfill, 0, sizeof(int) * N_NODES, sC);
    hist_kernel<<<(N_EDGES + 255) / 256, 256, 0, sC>>>(ei);
    scan1_kernel<<<N_SBLK, SCAN_B, 0, sC>>>();
    scan2_kernel<<<1, 256, 0, sC>>>();
    scan3_kernel<<<N_SBLK, SCAN_B, 0, sC>>>();
    fill_kernel<<<(N_EDGES + 255) / 256, 256, 0, sC>>>(ei, dij, dir);

    // chain A: embed MLP + pack epilogue
    embed_kernel<<<(N_NODES + BM - 1) / BM, 256, SMEM_EMBED_BYTES>>>(
        s, v, W1, b1, W2, b2);

    cudaEventRecord(eJoinC, sC);
    cudaStreamWaitEvent(0, eJoinC, 0);

    gather_kernel<<<(N_NODES + 1) / 2, 128>>>(v, s, Wd, bd, out);
}